// round 1
// baseline (speedup 1.0000x reference)
#include <cuda_runtime.h>
#include <cuda_bf16.h>
#include <cstdint>

// ---------------------------------------------------------------------------
// Problem constants (shapes fixed by the dataset): N=500000, D=128, G=10000,
// OUT=128, K=5*D=640. We still derive N and G at launch from in_sizes/out_size.
// ---------------------------------------------------------------------------
#define D       128
#define KTOT    640          // 5*D
#define MAXG    10048        // padded segment capacity for scratch

// Scratch (device globals; no allocation allowed)
__device__ int g_segoff[MAXG + 1];
__device__ __align__(16) __nv_bfloat16 g_fhi[(size_t)MAXG * KTOT];
__device__ __align__(16) __nv_bfloat16 g_flo[(size_t)MAXG * KTOT];
__device__ __align__(16) __nv_bfloat16 g_whi[KTOT * 128];
__device__ __align__(16) __nv_bfloat16 g_wlo[KTOT * 128];

// ---------------------------------------------------------------------------
// Kernel 1: segment start offsets via binary search on sorted batch ids.
// batch may be int64 or int32 (JAX x64 ambiguity). Detect: if int64, words
// [0, N) are (low,0) pairs -> word[N-1] == 0. If int32, word[N-1] = max id > 0.
// Reading words [0, N) is safe for either dtype.
// ---------------------------------------------------------------------------
__global__ void seg_offsets_kernel(const int* __restrict__ words, int N, int G)
{
    int g = blockIdx.x * blockDim.x + threadIdx.x;
    if (g > G) return;
    const bool is64 = (words[N - 1] == 0);
    int lo = 0, hi = N;
    while (lo < hi) {
        int mid = (lo + hi) >> 1;
        int v = is64 ? words[2 * mid] : words[mid];  // low word == value (0 <= id < 2^31)
        if (v < g) lo = mid + 1; else hi = mid;
    }
    g_segoff[g] = lo;
}

// ---------------------------------------------------------------------------
// Kernel 2: per-segment reduction. One block per segment, one thread per
// feature column. Streams 256MB of x; writes feats as bf16 hi/lo split.
// feats row layout: [sum/sqrt(50) | mean | min | max | std] (5 x 128)
// ---------------------------------------------------------------------------
__device__ __forceinline__ void store_split(size_t idx, float f)
{
    __nv_bfloat16 h = __float2bfloat16(f);
    g_fhi[idx] = h;
    g_flo[idx] = __float2bfloat16(f - __bfloat162float(h));
}

__global__ __launch_bounds__(128) void seg_reduce_kernel(const float* __restrict__ x, int G)
{
    int g = blockIdx.x;
    int d = threadIdx.x;
    int s = g_segoff[g];
    int e = g_segoff[g + 1];
    int cnt = e - s;

    float sum = 0.f, sq = 0.f;
    float mn = __int_as_float(0x7f800000);   // +inf
    float mx = __int_as_float(0xff800000);   // -inf

    const float* p = x + (size_t)s * D + d;
    int i = 0;
    for (; i + 4 <= cnt; i += 4) {
        float v0 = p[0];
        float v1 = p[D];
        float v2 = p[2 * D];
        float v3 = p[3 * D];
        p += 4 * D;
        sum += v0; sq += v0 * v0; mn = fminf(mn, v0); mx = fmaxf(mx, v0);
        sum += v1; sq += v1 * v1; mn = fminf(mn, v1); mx = fmaxf(mx, v1);
        sum += v2; sq += v2 * v2; mn = fminf(mn, v2); mx = fmaxf(mx, v2);
        sum += v3; sq += v3 * v3; mn = fminf(mn, v3); mx = fmaxf(mx, v3);
    }
    for (; i < cnt; ++i) {
        float v = p[0]; p += D;
        sum += v; sq += v * v; mn = fminf(mn, v); mx = fmaxf(mx, v);
    }

    float fc   = fmaxf((float)cnt, 1.0f);
    float mean = sum / fc;
    float msq  = sq / fc;
    float stdv = sqrtf(fmaxf(msq - mean * mean, 1e-9f));
    if (cnt == 0) { mn = 0.f; mx = 0.f; }   // never happens for this data

    size_t base = (size_t)g * KTOT + d;
    store_split(base + 0 * D, sum * 0.14142135623730951f);  // 1/sqrt(AVG_NODES=50)
    store_split(base + 1 * D, mean);
    store_split(base + 2 * D, mn);
    store_split(base + 3 * D, mx);
    store_split(base + 4 * D, stdv);
}

// ---------------------------------------------------------------------------
// Kernel 3: split W (f32 [640,128]) into bf16 hi/lo.
// ---------------------------------------------------------------------------
__global__ void w_split_kernel(const float* __restrict__ W)
{
    int i = blockIdx.x * blockDim.x + threadIdx.x;
    if (i >= KTOT * 128) return;
    float v = W[i];
    __nv_bfloat16 h = __float2bfloat16(v);
    g_whi[i] = h;
    g_wlo[i] = __float2bfloat16(v - __bfloat162float(h));
}

// ---------------------------------------------------------------------------
// Kernel 4: GEMM out[G,128] = feats[G,640] @ W[640,128] + bias, fp32 accum,
// bf16x2 error compensation: AhiBhi + AhiBlo + AloBhi (3 passes, same accum).
// BM=64, BN=128, BK=64. 256 threads = 8 warps (2 x 4), warp tile 32x32,
// mma.sync.aligned.m16n8k16.row.col.f32.bf16.bf16.f32.
// ---------------------------------------------------------------------------
#define ASTRIDE 68    // bf16 elems per A smem row (padded vs 64)
#define BSTRIDE 132   // bf16 elems per B smem row (padded vs 128)

__global__ __launch_bounds__(256) void gemm_kernel(const float* __restrict__ bias,
                                                   float* __restrict__ out, int G)
{
    __shared__ __align__(16) __nv_bfloat16 As[64 * ASTRIDE];
    __shared__ __align__(16) __nv_bfloat16 Bs[64 * BSTRIDE];

    int tid  = threadIdx.x;
    int warp = tid >> 5;
    int lane = tid & 31;
    int wm   = warp >> 2;        // 0..1  (M dim)
    int wn   = warp & 3;         // 0..3  (N dim)
    int bm   = blockIdx.x * 64;

    float acc[2][4][4];
    #pragma unroll
    for (int mt = 0; mt < 2; ++mt)
        #pragma unroll
        for (int nt = 0; nt < 4; ++nt)
            #pragma unroll
            for (int r = 0; r < 4; ++r) acc[mt][nt][r] = 0.f;

    const __nv_bfloat16* AP[3] = { g_fhi, g_fhi, g_flo };
    const __nv_bfloat16* BP[3] = { g_whi, g_wlo, g_whi };

    for (int pass = 0; pass < 3; ++pass) {
        const __nv_bfloat16* Ap = AP[pass];
        const __nv_bfloat16* Bp = BP[pass];
        for (int kt = 0; kt < KTOT / 64; ++kt) {
            int kb = kt * 64;
            __syncthreads();
            // Load A tile: 64 rows x 64 bf16 = 2048 u32 words, 8 per thread
            #pragma unroll
            for (int i = 0; i < 8; ++i) {
                int w   = tid + i * 256;
                int row = w >> 5;
                int cw  = w & 31;
                unsigned val = 0;
                int gr = bm + row;
                if (gr < G)
                    val = *(const unsigned*)(Ap + (size_t)gr * KTOT + kb + cw * 2);
                *(unsigned*)(As + row * ASTRIDE + cw * 2) = val;
            }
            // Load B tile: 64 k-rows x 128 n = 4096 words, 16 per thread
            #pragma unroll
            for (int i = 0; i < 16; ++i) {
                int w  = tid + i * 256;
                int k  = w >> 6;
                int nw = w & 63;
                unsigned val = *(const unsigned*)(Bp + (size_t)(kb + k) * 128 + nw * 2);
                *(unsigned*)(Bs + k * BSTRIDE + nw * 2) = val;
            }
            __syncthreads();

            #pragma unroll
            for (int ks = 0; ks < 4; ++ks) {
                int k0 = ks * 16;
                unsigned a[2][4];
                #pragma unroll
                for (int mt = 0; mt < 2; ++mt) {
                    int row = wm * 32 + mt * 16 + (lane >> 2);
                    int c   = k0 + (lane & 3) * 2;
                    const __nv_bfloat16* ab = As + row * ASTRIDE + c;
                    a[mt][0] = *(const unsigned*)(ab);
                    a[mt][1] = *(const unsigned*)(ab + 8 * ASTRIDE);
                    a[mt][2] = *(const unsigned*)(ab + 8);
                    a[mt][3] = *(const unsigned*)(ab + 8 * ASTRIDE + 8);
                }
                #pragma unroll
                for (int nt = 0; nt < 4; ++nt) {
                    int n  = wn * 32 + nt * 8 + (lane >> 2);
                    int kk = k0 + (lane & 3) * 2;
                    const __nv_bfloat16* bb = Bs + kk * BSTRIDE + n;
                    unsigned short x0 = *(const unsigned short*)(bb);
                    unsigned short x1 = *(const unsigned short*)(bb + BSTRIDE);
                    unsigned short x2 = *(const unsigned short*)(bb + 8 * BSTRIDE);
                    unsigned short x3 = *(const unsigned short*)(bb + 9 * BSTRIDE);
                    unsigned b0 = (unsigned)x0 | ((unsigned)x1 << 16);
                    unsigned b1 = (unsigned)x2 | ((unsigned)x3 << 16);
                    #pragma unroll
                    for (int mt = 0; mt < 2; ++mt) {
                        asm volatile(
                            "mma.sync.aligned.m16n8k16.row.col.f32.bf16.bf16.f32 "
                            "{%0,%1,%2,%3}, {%4,%5,%6,%7}, {%8,%9}, {%0,%1,%2,%3};\n"
                            : "+f"(acc[mt][nt][0]), "+f"(acc[mt][nt][1]),
                              "+f"(acc[mt][nt][2]), "+f"(acc[mt][nt][3])
                            : "r"(a[mt][0]), "r"(a[mt][1]), "r"(a[mt][2]), "r"(a[mt][3]),
                              "r"(b0), "r"(b1));
                    }
                }
            }
        }
    }

    // Epilogue: fp32 store + bias
    #pragma unroll
    for (int mt = 0; mt < 2; ++mt) {
        #pragma unroll
        for (int nt = 0; nt < 4; ++nt) {
            int row = bm + wm * 32 + mt * 16 + (lane >> 2);
            int n   = wn * 32 + nt * 8 + (lane & 3) * 2;
            float b0 = bias[n];
            float b1 = bias[n + 1];
            if (row < G) {
                out[(size_t)row * 128 + n]     = acc[mt][nt][0] + b0;
                out[(size_t)row * 128 + n + 1] = acc[mt][nt][1] + b1;
            }
            if (row + 8 < G) {
                out[(size_t)(row + 8) * 128 + n]     = acc[mt][nt][2] + b0;
                out[(size_t)(row + 8) * 128 + n + 1] = acc[mt][nt][3] + b1;
            }
        }
    }
}

// ---------------------------------------------------------------------------
// Launch. Inputs (metadata order): x[f32 N*128], batch[int64/int32 N],
// W[f32 640*128], b[f32 128], num_segments (scalar, ignored; G = out_size/128).
// ---------------------------------------------------------------------------
extern "C" void kernel_launch(void* const* d_in, const int* in_sizes, int n_in,
                              void* d_out, int out_size)
{
    const float* x     = (const float*)d_in[0];
    const int*   batch = (const int*)d_in[1];   // raw words; dtype detected on device
    const float* W     = (const float*)d_in[2];
    const float* bias  = (const float*)d_in[3];
    float*       out   = (float*)d_out;

    int N = in_sizes[0] / D;
    int G = out_size / 128;

    seg_offsets_kernel<<<(G + 256) / 256, 256>>>(batch, N, G);
    w_split_kernel<<<(KTOT * 128 + 255) / 256, 256>>>(W);
    seg_reduce_kernel<<<G, 128>>>(x, G);
    gemm_kernel<<<(G + 63) / 64, 256>>>(bias, out, G);
}

// round 2
// speedup vs baseline: 3.1178x; 3.1178x over previous
#include <cuda_runtime.h>
#include <cuda_bf16.h>
#include <cstdint>

// ---------------------------------------------------------------------------
// N=500000, D=128, G=10000, OUT=128, K=5*D=640 (derived at launch anyway).
// ---------------------------------------------------------------------------
#define D       128
#define KTOT    640
#define MAXG    10048        // padded segment capacity (multiple of 64)

// Scratch (device globals; zero-initialized at module load)
__device__ int g_segoff[MAXG + 1];
__device__ __align__(16) __nv_bfloat16 g_fhi[(size_t)MAXG * KTOT];  // feats hi
__device__ __align__(16) __nv_bfloat16 g_flo[(size_t)MAXG * KTOT];  // feats lo
// W stored TRANSPOSED: [n=128][k=640] so B fragments are contiguous in k.
__device__ __align__(16) __nv_bfloat16 g_whi[128 * KTOT];
__device__ __align__(16) __nv_bfloat16 g_wlo[128 * KTOT];

// ---------------------------------------------------------------------------
// Kernel 1: segment start offsets via binary search on sorted batch ids.
// batch may be int64 or int32; detect via word[N-1] (int64 -> high word 0).
// ---------------------------------------------------------------------------
__global__ void seg_offsets_kernel(const int* __restrict__ words, int N, int G)
{
    int g = blockIdx.x * blockDim.x + threadIdx.x;
    if (g > G) return;
    const bool is64 = (words[N - 1] == 0);
    int lo = 0, hi = N;
    while (lo < hi) {
        int mid = (lo + hi) >> 1;
        int v = is64 ? words[2 * mid] : words[mid];
        if (v < g) lo = mid + 1; else hi = mid;
    }
    g_segoff[g] = lo;
}

// ---------------------------------------------------------------------------
// Kernel 2: per-segment reduction (HBM-bound streaming of 256MB).
// One block per segment, one thread per feature column.
// feats row layout: [sum/sqrt(50) | mean | min | max | std] (5 x 128)
// ---------------------------------------------------------------------------
__device__ __forceinline__ void store_split(size_t idx, float f)
{
    __nv_bfloat16 h = __float2bfloat16(f);
    g_fhi[idx] = h;
    g_flo[idx] = __float2bfloat16(f - __bfloat162float(h));
}

__global__ __launch_bounds__(128) void seg_reduce_kernel(const float* __restrict__ x, int G)
{
    int g = blockIdx.x;
    int d = threadIdx.x;
    int s = g_segoff[g];
    int e = g_segoff[g + 1];
    int cnt = e - s;

    float sum = 0.f, sq = 0.f;
    float mn = __int_as_float(0x7f800000);
    float mx = __int_as_float(0xff800000);

    const float* p = x + (size_t)s * D + d;
    int i = 0;
    for (; i + 4 <= cnt; i += 4) {
        float v0 = p[0];
        float v1 = p[D];
        float v2 = p[2 * D];
        float v3 = p[3 * D];
        p += 4 * D;
        sum += v0; sq += v0 * v0; mn = fminf(mn, v0); mx = fmaxf(mx, v0);
        sum += v1; sq += v1 * v1; mn = fminf(mn, v1); mx = fmaxf(mx, v1);
        sum += v2; sq += v2 * v2; mn = fminf(mn, v2); mx = fmaxf(mx, v2);
        sum += v3; sq += v3 * v3; mn = fminf(mn, v3); mx = fmaxf(mx, v3);
    }
    for (; i < cnt; ++i) {
        float v = p[0]; p += D;
        sum += v; sq += v * v; mn = fminf(mn, v); mx = fmaxf(mx, v);
    }

    float fc   = fmaxf((float)cnt, 1.0f);
    float mean = sum / fc;
    float msq  = sq / fc;
    float stdv = sqrtf(fmaxf(msq - mean * mean, 1e-9f));
    if (cnt == 0) { mn = 0.f; mx = 0.f; }

    size_t base = (size_t)g * KTOT + d;
    store_split(base + 0 * D, sum * 0.14142135623730951f);  // 1/sqrt(50)
    store_split(base + 1 * D, mean);
    store_split(base + 2 * D, mn);
    store_split(base + 3 * D, mx);
    store_split(base + 4 * D, stdv);
}

// ---------------------------------------------------------------------------
// Kernel 3: split + transpose W (f32 [640,128] -> bf16 hi/lo [128][640]).
// Output-linear mapping: writes coalesced, reads served by L1/L2.
// ---------------------------------------------------------------------------
__global__ void w_split_kernel(const float* __restrict__ W)
{
    int j = blockIdx.x * blockDim.x + threadIdx.x;
    if (j >= 128 * KTOT) return;
    int n = j / KTOT;
    int k = j - n * KTOT;
    float v = W[(size_t)k * 128 + n];
    __nv_bfloat16 h = __float2bfloat16(v);
    g_whi[j] = h;
    g_wlo[j] = __float2bfloat16(v - __bfloat162float(h));
}

// ---------------------------------------------------------------------------
// Kernel 4: GEMM out[G,128] = feats[G,640] @ W[640,128] + bias.
// Fused 3-combo bf16 compensation (AhiBhi + AhiBlo + AloBhi) in a single
// K loop, cp.async 2-stage double buffer, conflict-free 32-bit LDS frags.
// BM=64, BN=128, BK=64; 256 threads = 8 warps (2M x 4N), warp tile 32x32.
// ---------------------------------------------------------------------------
#define SSTR    72                 // smem row stride in bf16 (144B: conflict-free)
#define A_BUF   (64 * SSTR)        // 4608 elems, one A buffer
#define B_BUF   (128 * SSTR)       // 9216 elems, one B buffer
#define A_STAGE (2 * A_BUF)        // hi+lo per stage
#define B_BASE  (2 * A_STAGE)
#define B_STAGE (2 * B_BUF)
#define SMEM_ELEMS (B_BASE + 2 * B_STAGE)   // 55296 elems = 110592 B

__device__ __forceinline__ void cp16(__nv_bfloat16* dst, const __nv_bfloat16* src)
{
    unsigned sa = (unsigned)__cvta_generic_to_shared(dst);
    asm volatile("cp.async.cg.shared.global [%0], [%1], 16;\n" :: "r"(sa), "l"(src));
}

#define MMA_BF16(acc, a, b0, b1)                                              \
    asm volatile(                                                             \
        "mma.sync.aligned.m16n8k16.row.col.f32.bf16.bf16.f32 "                \
        "{%0,%1,%2,%3}, {%4,%5,%6,%7}, {%8,%9}, {%0,%1,%2,%3};\n"             \
        : "+f"((acc)[0]), "+f"((acc)[1]), "+f"((acc)[2]), "+f"((acc)[3])      \
        : "r"((a)[0]), "r"((a)[1]), "r"((a)[2]), "r"((a)[3]),                 \
          "r"(b0), "r"(b1))

__global__ __launch_bounds__(256) void gemm_kernel(const float* __restrict__ bias,
                                                   float* __restrict__ out, int G)
{
    extern __shared__ __nv_bfloat16 sm[];
    int tid  = threadIdx.x;
    int warp = tid >> 5;
    int lane = tid & 31;
    int wm   = warp >> 2;
    int wn   = warp & 3;
    int bm   = blockIdx.x * 64;

    float acc[2][4][4];
    #pragma unroll
    for (int mt = 0; mt < 2; ++mt)
        #pragma unroll
        for (int nt = 0; nt < 4; ++nt)
            #pragma unroll
            for (int r = 0; r < 4; ++r) acc[mt][nt][r] = 0.f;

    // -------- stage loader: 3072 x 16B cp.async, 12 per thread -----------
    auto load_stage = [&](int s, int kt) {
        int kb = kt * 64;
        #pragma unroll
        for (int i = 0; i < 12; ++i) {
            int c = tid + i * 256;
            if (c < 1024) {                       // A tiles (hi then lo)
                int hl  = c >> 9;
                int cc  = c & 511;
                int row = cc >> 3;
                int cw  = cc & 7;
                const __nv_bfloat16* src =
                    (hl ? g_flo : g_fhi) + (size_t)(bm + row) * KTOT + kb + cw * 8;
                cp16(sm + s * A_STAGE + hl * A_BUF + row * SSTR + cw * 8, src);
            } else {                              // B tiles (hi then lo)
                int c2  = c - 1024;
                int hl  = c2 >> 10;
                int cc  = c2 & 1023;
                int row = cc >> 3;                // n
                int cw  = cc & 7;
                const __nv_bfloat16* src =
                    (hl ? g_wlo : g_whi) + (size_t)row * KTOT + kb + cw * 8;
                cp16(sm + B_BASE + s * B_STAGE + hl * B_BUF + row * SSTR + cw * 8, src);
            }
        }
    };

    load_stage(0, 0);
    asm volatile("cp.async.commit_group;\n");

    for (int kt = 0; kt < KTOT / 64; ++kt) {
        int s = kt & 1;
        if (kt + 1 < KTOT / 64) {
            load_stage(s ^ 1, kt + 1);
            asm volatile("cp.async.commit_group;\n");
            asm volatile("cp.async.wait_group 1;\n");
        } else {
            asm volatile("cp.async.wait_group 0;\n");
        }
        __syncthreads();

        const __nv_bfloat16* Ah = sm + s * A_STAGE;
        const __nv_bfloat16* Al = Ah + A_BUF;
        const __nv_bfloat16* Bh = sm + B_BASE + s * B_STAGE;
        const __nv_bfloat16* Bl = Bh + B_BUF;

        #pragma unroll
        for (int ks = 0; ks < 4; ++ks) {
            int k0 = ks * 16;
            unsigned ah[2][4], al[2][4];
            #pragma unroll
            for (int mt = 0; mt < 2; ++mt) {
                int row = wm * 32 + mt * 16 + (lane >> 2);
                int col = k0 + (lane & 3) * 2;
                const __nv_bfloat16* p = Ah + row * SSTR + col;
                ah[mt][0] = *(const unsigned*)(p);
                ah[mt][1] = *(const unsigned*)(p + 8 * SSTR);
                ah[mt][2] = *(const unsigned*)(p + 8);
                ah[mt][3] = *(const unsigned*)(p + 8 * SSTR + 8);
                const __nv_bfloat16* q = Al + row * SSTR + col;
                al[mt][0] = *(const unsigned*)(q);
                al[mt][1] = *(const unsigned*)(q + 8 * SSTR);
                al[mt][2] = *(const unsigned*)(q + 8);
                al[mt][3] = *(const unsigned*)(q + 8 * SSTR + 8);
            }
            #pragma unroll
            for (int nt = 0; nt < 4; ++nt) {
                int n   = wn * 32 + nt * 8 + (lane >> 2);
                int col = k0 + (lane & 3) * 2;
                const __nv_bfloat16* pb = Bh + n * SSTR + col;
                unsigned bh0 = *(const unsigned*)(pb);
                unsigned bh1 = *(const unsigned*)(pb + 8);
                const __nv_bfloat16* qb = Bl + n * SSTR + col;
                unsigned bl0 = *(const unsigned*)(qb);
                unsigned bl1 = *(const unsigned*)(qb + 8);
                #pragma unroll
                for (int mt = 0; mt < 2; ++mt) {
                    MMA_BF16(acc[mt][nt], ah[mt], bh0, bh1);
                    MMA_BF16(acc[mt][nt], ah[mt], bl0, bl1);
                    MMA_BF16(acc[mt][nt], al[mt], bh0, bh1);
                }
            }
        }
        __syncthreads();
    }

    // Epilogue: fp32 + bias
    #pragma unroll
    for (int mt = 0; mt < 2; ++mt) {
        #pragma unroll
        for (int nt = 0; nt < 4; ++nt) {
            int row = bm + wm * 32 + mt * 16 + (lane >> 2);
            int n   = wn * 32 + nt * 8 + (lane & 3) * 2;
            float b0 = bias[n];
            float b1 = bias[n + 1];
            if (row < G) {
                out[(size_t)row * 128 + n]     = acc[mt][nt][0] + b0;
                out[(size_t)row * 128 + n + 1] = acc[mt][nt][1] + b1;
            }
            if (row + 8 < G) {
                out[(size_t)(row + 8) * 128 + n]     = acc[mt][nt][2] + b0;
                out[(size_t)(row + 8) * 128 + n + 1] = acc[mt][nt][3] + b1;
            }
        }
    }
}

// ---------------------------------------------------------------------------
// Launch. Inputs: x[f32 N*128], batch[int64/int32 N], W[f32 640*128],
// b[f32 128], num_segments (ignored; G = out_size/128).
// ---------------------------------------------------------------------------
extern "C" void kernel_launch(void* const* d_in, const int* in_sizes, int n_in,
                              void* d_out, int out_size)
{
    const float* x     = (const float*)d_in[0];
    const int*   batch = (const int*)d_in[1];
    const float* W     = (const float*)d_in[2];
    const float* bias  = (const float*)d_in[3];
    float*       out   = (float*)d_out;

    int N = in_sizes[0] / D;
    int G = out_size / 128;

    static bool attr_done = false;
    if (!attr_done) {
        cudaFuncSetAttribute(gemm_kernel,
                             cudaFuncAttributeMaxDynamicSharedMemorySize,
                             SMEM_ELEMS * (int)sizeof(__nv_bfloat16));
        attr_done = true;
    }

    seg_offsets_kernel<<<(G + 256) / 256, 256>>>(batch, N, G);
    w_split_kernel<<<(128 * KTOT + 255) / 256, 256>>>(W);
    seg_reduce_kernel<<<G, 128>>>(x, G);
    gemm_kernel<<<(G + 63) / 64, 256, SMEM_ELEMS * sizeof(__nv_bfloat16)>>>(bias, out, G);
}